// round 12
// baseline (speedup 1.0000x reference)
#include <cuda_runtime.h>
#include <cstdint>

#define HW 1024
#define PLANE (HW * HW)
#define BMAX 16

// Ping-pong scratch for the low-pass images (allocation-free rule).
static __device__ float g_lowA[BMAX * PLANE];
static __device__ float g_lowB[BMAX * PLANE];
// Monotonic grid-barrier counter (replay-safe: never reset).
static __device__ unsigned int g_bar;

__device__ __forceinline__ int refl(int i) {
    // jnp.pad 'symmetric': -1 -> 0, -2 -> 1, N -> N-1
    if (i < 0)   i = -1 - i;
    if (i >= HW) i = 2 * HW - 1 - i;
    return i;
}

// Grid-wide barrier. All CTAs are guaranteed co-resident (512 blocks,
// launch_bounds(256,4) -> 592 slots). Monotonic counter: round-robust across
// graph replays without any reset.
__device__ __forceinline__ void grid_barrier() {
    __syncthreads();
    if (threadIdx.x == 0) {
        __threadfence();                                   // release
        const unsigned nb  = gridDim.x;
        const unsigned old = atomicAdd(&g_bar, 1u);
        const unsigned target = (old / nb + 1u) * nb;
        unsigned v;
        do { v = *(volatile unsigned*)&g_bar; } while ((int)(v - target) < 0);
        __threadfence();                                   // acquire
    }
    __syncthreads();
}

// One starlet scale (R5-proven body). Vertical dilated-by-D conv == plain
// 5-tap conv on each of D row-subsampled sub-images. 256 threads = one full
// 1024-float row. R=2 slabs; vertical results v0,v1 stay in registers across
// the barrier as the horizontal center tap; next slab's 2 LDG.128 issue before
// the barrier; double-buffered smem -> one __syncthreads per slab.
template<int D, int SRC, int DST>
__device__ void scale_body(const float* __restrict__ ext_in,
                           float* __restrict__ coeff_out,
                           const float inv, const int b, const int resid,
                           const int s0, float* __restrict__ smb)
{
    constexpr int S = 32;
    constexpr int NSLAB = S / 2;
    constexpr float W0 = 1.0f / 16.0f;
    constexpr float W1 = 1.0f / 4.0f;
    constexpr float W2 = 3.0f / 8.0f;
    constexpr int SMS = HW + 4;           // smem row stride

    const int t  = threadIdx.x;           // f4 column 0..255
    const int x4 = 4 * t;

    const float* src  = (SRC == 0) ? ext_in : (SRC == 1 ? g_lowA : g_lowB);
    const float* simg = src + (size_t)b * PLANE;
    float* lowp = (DST == 0) ? nullptr
                : ((DST == 1) ? g_lowA : g_lowB) + (size_t)b * PLANE;
    const size_t step = (size_t)D * HW;

    auto vcomb = [](const float4& a, const float4& bb, const float4& c,
                    const float4& d, const float4& e) -> float4 {
        float4 v;
        v.x = W0 * (a.x + e.x) + W1 * (bb.x + d.x) + W2 * c.x;
        v.y = W0 * (a.y + e.y) + W1 * (bb.y + d.y) + W2 * c.y;
        v.z = W0 * (a.z + e.z) + W1 * (bb.z + d.z) + W2 * c.z;
        v.w = W0 * (a.w + e.w) + W1 * (bb.w + d.w) + W2 * c.w;
        return v;
    };

    auto run = [&](auto&& ldnext) {
        float4 w0 = ldnext(), w1 = ldnext(), w2 = ldnext(), w3 = ldnext();
        float4 n0 = ldnext(), n1 = ldnext();

        float* cp = coeff_out + ((size_t)b * HW + (size_t)(resid + D * s0)) * HW + x4;
        float* lp = (DST != 0) ? lowp + (size_t)(resid + D * s0) * HW + x4 : nullptr;

        #pragma unroll 4
        for (int slab = 0; slab < NSLAB; slab++) {
            float* smbuf = smb + (slab & 1) * (2 * SMS);

            // vertical 5-tap; results stay in regs as horizontal centers
            const float4 v0 = vcomb(w0, w1, w2, w3, n0);
            const float4 v1 = vcomb(w1, w2, w3, n0, n1);
            *reinterpret_cast<float4*>(&smbuf[x4])       = v0;
            *reinterpret_cast<float4*>(&smbuf[SMS + x4]) = v1;

            // shift window (raw centers become new w0,w1)
            w0 = w2; w1 = w3; w2 = n0; w3 = n1;

            // prefetch next slab's rows (in flight across the barrier)
            if (slab + 1 < NSLAB) { n0 = ldnext(); n1 = ldnext(); }

            __syncthreads();

            #pragma unroll
            for (int r = 0; r < 2; r++) {
                const float* smrow = smbuf + r * SMS;
                const float4 vc  = (r == 0) ? v0 : v1;
                const float4 raw = (r == 0) ? w0 : w1;
                float4 low;

                if constexpr (D >= 4) {
                    constexpr int G = D / 4;
                    if (t >= 2 * G && t <= 255 - 2 * G) {
                        const float4 a  = *reinterpret_cast<const float4*>(&smrow[x4 - 8 * G]);
                        const float4 bb = *reinterpret_cast<const float4*>(&smrow[x4 - 4 * G]);
                        const float4 d  = *reinterpret_cast<const float4*>(&smrow[x4 + 4 * G]);
                        const float4 e  = *reinterpret_cast<const float4*>(&smrow[x4 + 8 * G]);
                        low = vcomb(a, bb, vc, d, e);
                    } else {
                        float lo[4];
                        #pragma unroll
                        for (int j = 0; j < 4; j++) {
                            const int e0 = x4 + j;
                            auto g = [&](int m) -> float {
                                int e = e0 + m;
                                if (e < 0)   e = -1 - e;
                                if (e >= HW) e = 2 * HW - 1 - e;
                                return smrow[e];
                            };
                            lo[j] = W0 * (g(-2 * D) + g(2 * D))
                                  + W1 * (g(-D) + g(D)) + W2 * g(0);
                        }
                        low.x = lo[0]; low.y = lo[1]; low.z = lo[2]; low.w = lo[3];
                    }
                } else {
                    if (t >= 1 && t <= 254) {
                        float fl[12];
                        *reinterpret_cast<float4*>(&fl[0]) = *reinterpret_cast<const float4*>(&smrow[x4 - 4]);
                        fl[4] = vc.x; fl[5] = vc.y; fl[6] = vc.z; fl[7] = vc.w;
                        *reinterpret_cast<float4*>(&fl[8]) = *reinterpret_cast<const float4*>(&smrow[x4 + 4]);
                        float lo[4];
                        #pragma unroll
                        for (int j = 0; j < 4; j++) {
                            lo[j] = W0 * (fl[4 + j - 2 * D] + fl[4 + j + 2 * D])
                                  + W1 * (fl[4 + j - D]     + fl[4 + j + D])
                                  + W2 *  fl[4 + j];
                        }
                        low.x = lo[0]; low.y = lo[1]; low.z = lo[2]; low.w = lo[3];
                    } else {
                        float lo[4];
                        #pragma unroll
                        for (int j = 0; j < 4; j++) {
                            const int e0 = x4 + j;
                            auto g = [&](int m) -> float {
                                int e = e0 + m;
                                if (e < 0)   e = -1 - e;
                                if (e >= HW) e = 2 * HW - 1 - e;
                                return smrow[e];
                            };
                            lo[j] = W0 * (g(-2 * D) + g(2 * D))
                                  + W1 * (g(-D) + g(D)) + W2 * g(0);
                        }
                        low.x = lo[0]; low.y = lo[1]; low.z = lo[2]; low.w = lo[3];
                    }
                }

                float4 cf;
                cf.x = (raw.x - low.x) * inv;
                cf.y = (raw.y - low.y) * inv;
                cf.z = (raw.z - low.z) * inv;
                cf.w = (raw.w - low.w) * inv;

                __stcs(reinterpret_cast<float4*>(cp), cf);   // streaming store
                cp += step;
                if (DST != 0) {
                    *reinterpret_cast<float4*>(lp) = low;    // keep in L2
                    lp += step;
                }
            }
            // double-buffered smem: no trailing barrier
        }
    };

    const int HWsub = HW / D;
    if (s0 >= 2 && s0 + S + 2 <= HWsub) {
        const float* p = simg + (size_t)(resid + D * (s0 - 2)) * HW + x4;
        run([&]() -> float4 {
            const float4 v = *reinterpret_cast<const float4*>(p);
            p += step;
            return v;
        });
    } else {
        int s = s0 - 2;
        run([&]() -> float4 {
            const int f = refl(resid + D * s);
            s++;
            return *reinterpret_cast<const float4*>(simg + (size_t)f * HW + x4);
        });
    }
}

// Fused 4-scale kernel: 512 co-resident blocks, 3 software grid barriers.
// Per batch: 32 blocks; for scale with dilation D: resid = r % D, strip = r / D
// (every scale has exactly 32 blocks/batch: D residues x 32/D strips).
__global__ __launch_bounds__(256, 4)
void starlet_fused(const float* __restrict__ image,
                   const float* __restrict__ norms,
                   float* __restrict__ out, size_t plane_all)
{
    __shared__ __align__(16) float smb[4 * (HW + 4)];

    const int flat = blockIdx.x;
    const int b    = flat >> 5;     // batch
    const int r    = flat & 31;     // block-within-batch

    const float i0 = 1.0f / norms[0];
    const float i1 = 1.0f / norms[1];
    const float i2 = 1.0f / norms[2];
    const float i3 = 1.0f / norms[3];

    // scale 0: image -> lowA
    scale_body<1, 0, 1>(image, out + 0 * plane_all, i0, b, 0, r * 32, smb);
    grid_barrier();
    // scale 1: lowA -> lowB
    scale_body<2, 1, 2>(image, out + 1 * plane_all, i1, b, r & 1, (r >> 1) * 32, smb);
    grid_barrier();
    // scale 2: lowB -> lowA
    scale_body<4, 2, 1>(image, out + 2 * plane_all, i2, b, r & 3, (r >> 2) * 32, smb);
    grid_barrier();
    // scale 3: lowA -> (none)
    scale_body<8, 1, 0>(image, out + 3 * plane_all, i3, b, r & 7, (r >> 3) * 32, smb);
}

extern "C" void kernel_launch(void* const* d_in, const int* in_sizes, int n_in,
                              void* d_out, int out_size)
{
    int img_idx = 0, nrm_idx = 1;
    if (n_in >= 2 && in_sizes[0] == 4) { img_idx = 1; nrm_idx = 0; }

    const float* image = (const float*)d_in[img_idx];
    const float* norms = (const float*)d_in[nrm_idx];
    float* out = (float*)d_out;

    int B = in_sizes[img_idx] / PLANE;
    if (B < 1) B = 1;
    if (B > BMAX) B = BMAX;
    const size_t plane_all = (size_t)B * PLANE;

    // 32 blocks per batch image; B=16 -> 512 blocks, all co-resident at
    // 4 CTAs/SM on 148 SMs (592 slots) -> grid barrier is deadlock-free.
    starlet_fused<<<dim3(B * 32), dim3(256)>>>(image, norms, out, plane_all);
}

// round 13
// speedup vs baseline: 1.3680x; 1.3680x over previous
#include <cuda_runtime.h>
#include <cstdint>

#define HW 1024
#define PLANE (HW * HW)
#define BMAX 16

// Ping-pong scratch for the low-pass images (allocation-free rule).
static __device__ float g_lowA[BMAX * PLANE];
static __device__ float g_lowB[BMAX * PLANE];

__device__ __forceinline__ int refl(int i) {
    // jnp.pad 'symmetric': -1 -> 0, -2 -> 1, N -> N-1
    if (i < 0)   i = -1 - i;
    if (i >= HW) i = 2 * HW - 1 - i;
    return i;
}

// One starlet scale (R5-proven body). Vertical dilated-by-D conv == plain
// 5-tap conv on each of D row-subsampled sub-images. Block = 256 threads =
// one full 1024-float row. blockIdx.y = residue, blockIdx.x = strip of S
// sub-rows, blockIdx.z = batch.
//
// R=2 slabs: vertical results v0,v1 stay in registers across the barrier and
// serve as the horizontal center tap. Next slab's two LDG.128 issue before
// the barrier. Double-buffered smem -> one __syncthreads per slab.
// STREAMRD: raw input is read for the last time (image at scale 0 / lowA at
// scale 3) -> __ldcs evict-first, preserving L2 for the low write->read chain.
template<int D, int SRC, int DST, bool STREAMRD>
__global__ __launch_bounds__(256, 4)
void starlet_stream(const float* __restrict__ ext_in,
                    const float* __restrict__ norms,
                    int scale,
                    float* __restrict__ coeff_out)
{
    constexpr int S = 32;     // sub-rows per block
    constexpr int NSLAB = S / 2;
    constexpr float W0 = 1.0f / 16.0f;
    constexpr float W1 = 1.0f / 4.0f;
    constexpr float W2 = 3.0f / 8.0f;

    __shared__ __align__(16) float sm[2][2][HW + 4];

    const int t     = threadIdx.x;        // float4 column 0..255
    const int resid = blockIdx.y;         // residue class
    const int s0    = blockIdx.x * S;     // first sub-row of strip
    const int b     = blockIdx.z;

    const float* src  = (SRC == 0) ? ext_in : (SRC == 1 ? g_lowA : g_lowB);
    const float* simg = src + (size_t)b * PLANE;
    float* lowdst = (DST == 1) ? g_lowA : (DST == 2 ? g_lowB : nullptr);
    if (DST != 0) lowdst += (size_t)b * PLANE;

    const int x4 = 4 * t;
    const float inv = 1.0f / norms[scale];
    const size_t step = (size_t)D * HW;   // float stride between sub-rows

    auto ld4 = [](const float* p) -> float4 {
        if constexpr (STREAMRD) return __ldcs(reinterpret_cast<const float4*>(p));
        else                    return *reinterpret_cast<const float4*>(p);
    };

    auto vcomb = [](const float4& a, const float4& bb, const float4& c,
                    const float4& d, const float4& e) -> float4 {
        float4 v;
        v.x = W0 * (a.x + e.x) + W1 * (bb.x + d.x) + W2 * c.x;
        v.y = W0 * (a.y + e.y) + W1 * (bb.y + d.y) + W2 * c.y;
        v.z = W0 * (a.z + e.z) + W1 * (bb.z + d.z) + W2 * c.z;
        v.w = W0 * (a.w + e.w) + W1 * (bb.w + d.w) + W2 * c.w;
        return v;
    };

    // Body, parameterized on a sequential row loader (calls return sub-rows
    // s0-2, s0-1, s0, ... in order; exactly S+4 calls).
    auto run = [&](auto&& ldnext) {
        float4 w0 = ldnext(), w1 = ldnext(), w2 = ldnext(), w3 = ldnext();
        float4 n0 = ldnext(), n1 = ldnext();

        float* cp = coeff_out + ((size_t)b * HW + (size_t)(resid + D * s0)) * HW + x4;
        float* lp = (DST != 0) ? lowdst + (size_t)(resid + D * s0) * HW + x4 : nullptr;

        #pragma unroll 4
        for (int slab = 0; slab < NSLAB; slab++) {
            const int buf = slab & 1;

            // ---- vertical 5-tap; results stay in regs as horizontal centers ----
            const float4 v0 = vcomb(w0, w1, w2, w3, n0);
            const float4 v1 = vcomb(w1, w2, w3, n0, n1);
            *reinterpret_cast<float4*>(&sm[buf][0][x4]) = v0;
            *reinterpret_cast<float4*>(&sm[buf][1][x4]) = v1;

            // shift window (raw centers become new w0,w1)
            w0 = w2; w1 = w3; w2 = n0; w3 = n1;

            // prefetch next slab's rows (in flight across the barrier)
            if (slab + 1 < NSLAB) { n0 = ldnext(); n1 = ldnext(); }

            __syncthreads();

            // ---- horizontal 5-tap (dilated by D along x), center from register ----
            #pragma unroll
            for (int r = 0; r < 2; r++) {
                const float4 vc  = (r == 0) ? v0 : v1;
                const float4 raw = (r == 0) ? w0 : w1;
                float4 low;

                if constexpr (D >= 4) {
                    constexpr int G = D / 4;           // tap offset in f4 groups
                    if (t >= 2 * G && t <= 255 - 2 * G) {
                        const float4 a  = *reinterpret_cast<const float4*>(&sm[buf][r][x4 - 8 * G]);
                        const float4 bb = *reinterpret_cast<const float4*>(&sm[buf][r][x4 - 4 * G]);
                        const float4 d  = *reinterpret_cast<const float4*>(&sm[buf][r][x4 + 4 * G]);
                        const float4 e  = *reinterpret_cast<const float4*>(&sm[buf][r][x4 + 8 * G]);
                        low = vcomb(a, bb, vc, d, e);
                    } else {
                        float lo[4];
                        #pragma unroll
                        for (int j = 0; j < 4; j++) {
                            const int e0 = x4 + j;
                            auto g = [&](int m) -> float {
                                int e = e0 + m;
                                if (e < 0)   e = -1 - e;
                                if (e >= HW) e = 2 * HW - 1 - e;
                                return sm[buf][r][e];
                            };
                            lo[j] = W0 * (g(-2 * D) + g(2 * D))
                                  + W1 * (g(-D) + g(D)) + W2 * g(0);
                        }
                        low.x = lo[0]; low.y = lo[1]; low.z = lo[2]; low.w = lo[3];
                    }
                } else {
                    if (t >= 1 && t <= 254) {
                        float fl[12];
                        *reinterpret_cast<float4*>(&fl[0]) = *reinterpret_cast<const float4*>(&sm[buf][r][x4 - 4]);
                        fl[4] = vc.x; fl[5] = vc.y; fl[6] = vc.z; fl[7] = vc.w;
                        *reinterpret_cast<float4*>(&fl[8]) = *reinterpret_cast<const float4*>(&sm[buf][r][x4 + 4]);
                        float lo[4];
                        #pragma unroll
                        for (int j = 0; j < 4; j++) {
                            lo[j] = W0 * (fl[4 + j - 2 * D] + fl[4 + j + 2 * D])
                                  + W1 * (fl[4 + j - D]     + fl[4 + j + D])
                                  + W2 *  fl[4 + j];
                        }
                        low.x = lo[0]; low.y = lo[1]; low.z = lo[2]; low.w = lo[3];
                    } else {
                        float lo[4];
                        #pragma unroll
                        for (int j = 0; j < 4; j++) {
                            const int e0 = x4 + j;
                            auto g = [&](int m) -> float {
                                int e = e0 + m;
                                if (e < 0)   e = -1 - e;
                                if (e >= HW) e = 2 * HW - 1 - e;
                                return sm[buf][r][e];
                            };
                            lo[j] = W0 * (g(-2 * D) + g(2 * D))
                                  + W1 * (g(-D) + g(D)) + W2 * g(0);
                        }
                        low.x = lo[0]; low.y = lo[1]; low.z = lo[2]; low.w = lo[3];
                    }
                }

                float4 cf;
                cf.x = (raw.x - low.x) * inv;
                cf.y = (raw.y - low.y) * inv;
                cf.z = (raw.z - low.z) * inv;
                cf.w = (raw.w - low.w) * inv;

                __stcs(reinterpret_cast<float4*>(cp), cf);  // streaming store
                cp += step;
                if (DST != 0) {
                    *reinterpret_cast<float4*>(lp) = low;   // keep in L2
                    lp += step;
                }
            }
            // double-buffered smem: no trailing barrier
        }
    };

    const int HWsub = HW / D;   // sub-image height
    if (s0 >= 2 && s0 + S + 2 <= HWsub) {
        // interior strip: pure incremental pointer, no reflection possible
        const float* p = simg + (size_t)(resid + D * (s0 - 2)) * HW + x4;
        run([&]() -> float4 {
            const float4 v = ld4(p);
            p += step;
            return v;
        });
    } else {
        // boundary strip: reflected row indices
        int s = s0 - 2;
        run([&]() -> float4 {
            const int f = refl(resid + D * s);
            s++;
            return ld4(simg + (size_t)f * HW + x4);
        });
    }
}

extern "C" void kernel_launch(void* const* d_in, const int* in_sizes, int n_in,
                              void* d_out, int out_size)
{
    int img_idx = 0, nrm_idx = 1;
    if (n_in >= 2 && in_sizes[0] == 4) { img_idx = 1; nrm_idx = 0; }

    const float* image = (const float*)d_in[img_idx];
    const float* norms = (const float*)d_in[nrm_idx];
    float* out = (float*)d_out;

    int B = in_sizes[img_idx] / PLANE;
    if (B < 1) B = 1;
    if (B > BMAX) B = BMAX;
    const size_t plane_all = (size_t)B * PLANE;

    const dim3 block(256);
    // grid: x = strips of 32 sub-rows, y = D residues, z = batch (512 blocks/scale)
    const dim3 g1(HW / (1 * 32), 1, B);
    const dim3 g2(HW / (2 * 32), 2, B);
    const dim3 g4(HW / (4 * 32), 4, B);
    const dim3 g8(HW / (8 * 32), 8, B);

    // scale 0: image (streaming read: read-once) -> lowA
    starlet_stream<1, 0, 1, true ><<<g1, block>>>(image, norms, 0, out + 0 * plane_all);
    // scale 1: lowA -> lowB (lowA stays cached: default read)
    starlet_stream<2, 1, 2, false><<<g2, block>>>(image, norms, 1, out + 1 * plane_all);
    // scale 2: lowB -> lowA
    starlet_stream<4, 2, 1, false><<<g4, block>>>(image, norms, 2, out + 2 * plane_all);
    // scale 3: lowA -> (none); last use of lowA -> streaming read
    starlet_stream<8, 1, 0, true ><<<g8, block>>>(image, norms, 3, out + 3 * plane_all);
}

// round 14
// speedup vs baseline: 1.4067x; 1.0283x over previous
#include <cuda_runtime.h>
#include <cstdint>

#define HW 1024
#define PLANE (HW * HW)
#define BMAX 16

// Ping-pong scratch for the low-pass images (allocation-free rule).
static __device__ float g_lowA[BMAX * PLANE];
static __device__ float g_lowB[BMAX * PLANE];

__device__ __forceinline__ int refl(int i) {
    // jnp.pad 'symmetric': -1 -> 0, -2 -> 1, N -> N-1
    if (i < 0)   i = -1 - i;
    if (i >= HW) i = 2 * HW - 1 - i;
    return i;
}

__device__ __forceinline__ float4 rev4(const float4 v) {
    float4 r; r.x = v.w; r.y = v.z; r.z = v.y; r.w = v.x; return r;
}

// One starlet scale. Vertical dilated-by-D conv == plain 5-tap conv on each of
// D row-subsampled sub-images. Block = 256 threads = one full 1024-float row.
// blockIdx.y = residue, blockIdx.x = strip of S sub-rows, blockIdx.z = batch.
//
// R=2 slabs: vertical results v0,v1 stay in registers across the barrier as
// the horizontal center tap; next slab's 2 LDG.128 issue before the barrier;
// double-buffered smem -> one __syncthreads per slab.
// NEW: each smem row carries a 16-float REFLECTED halo per side (threads 0-3 /
// 252-255 write rev4 of their own v). The horizontal pass is one uniform
// vectorized path for all 256 threads -- no divergence, no scalar edge loads.
template<int D, int SRC, int DST, bool STREAMRD>
__global__ __launch_bounds__(256, 4)
void starlet_stream(const float* __restrict__ ext_in,
                    const float* __restrict__ norms,
                    int scale,
                    float* __restrict__ coeff_out)
{
    constexpr int S = 32;                 // sub-rows per block
    constexpr int NSLAB = S / 2;
    constexpr int PAD = 16;               // halo floats per side (covers 2D<=16)
    constexpr int SMS = PAD + HW + PAD + 4;
    constexpr float W0 = 1.0f / 16.0f;
    constexpr float W1 = 1.0f / 4.0f;
    constexpr float W2 = 3.0f / 8.0f;

    __shared__ __align__(16) float sm[2][2][SMS];

    const int t     = threadIdx.x;        // float4 column 0..255
    const int resid = blockIdx.y;         // residue class
    const int s0    = blockIdx.x * S;     // first sub-row of strip
    const int b     = blockIdx.z;

    const float* src  = (SRC == 0) ? ext_in : (SRC == 1 ? g_lowA : g_lowB);
    const float* simg = src + (size_t)b * PLANE;
    float* lowdst = (DST == 1) ? g_lowA : (DST == 2 ? g_lowB : nullptr);
    if (DST != 0) lowdst += (size_t)b * PLANE;

    const int x4 = 4 * t;
    const int xb = PAD + x4;              // smem base index for this thread
    const float inv = 1.0f / norms[scale];
    const size_t step = (size_t)D * HW;   // float stride between sub-rows

    auto ld4 = [](const float* p) -> float4 {
        if constexpr (STREAMRD) return __ldcs(reinterpret_cast<const float4*>(p));
        else                    return *reinterpret_cast<const float4*>(p);
    };

    auto vcomb = [](const float4& a, const float4& bb, const float4& c,
                    const float4& d, const float4& e) -> float4 {
        float4 v;
        v.x = W0 * (a.x + e.x) + W1 * (bb.x + d.x) + W2 * c.x;
        v.y = W0 * (a.y + e.y) + W1 * (bb.y + d.y) + W2 * c.y;
        v.z = W0 * (a.z + e.z) + W1 * (bb.z + d.z) + W2 * c.z;
        v.w = W0 * (a.w + e.w) + W1 * (bb.w + d.w) + W2 * c.w;
        return v;
    };

    auto run = [&](auto&& ldnext) {
        float4 w0 = ldnext(), w1 = ldnext(), w2 = ldnext(), w3 = ldnext();
        float4 n0 = ldnext(), n1 = ldnext();

        float* cp = coeff_out + ((size_t)b * HW + (size_t)(resid + D * s0)) * HW + x4;
        float* lp = (DST != 0) ? lowdst + (size_t)(resid + D * s0) * HW + x4 : nullptr;

        #pragma unroll 4
        for (int slab = 0; slab < NSLAB; slab++) {
            const int buf = slab & 1;

            // ---- vertical 5-tap; results stay in regs as horizontal centers ----
            const float4 v0 = vcomb(w0, w1, w2, w3, n0);
            const float4 v1 = vcomb(w1, w2, w3, n0, n1);
            *reinterpret_cast<float4*>(&sm[buf][0][xb]) = v0;
            *reinterpret_cast<float4*>(&sm[buf][1][xb]) = v1;

            // reflected x-halo: ext col -1-k == col k ; ext col 1024+k == col 1023-k
            if (t < 4) {                                   // left halo f4 -(t+1)
                const int o = PAD - 4 * (t + 1);
                *reinterpret_cast<float4*>(&sm[buf][0][o]) = rev4(v0);
                *reinterpret_cast<float4*>(&sm[buf][1][o]) = rev4(v1);
            } else if (t >= 252) {                         // right halo f4 256+(255-t)
                const int o = PAD + HW + 4 * (255 - t);
                *reinterpret_cast<float4*>(&sm[buf][0][o]) = rev4(v0);
                *reinterpret_cast<float4*>(&sm[buf][1][o]) = rev4(v1);
            }

            // shift window (raw centers become new w0,w1)
            w0 = w2; w1 = w3; w2 = n0; w3 = n1;

            // prefetch next slab's rows (in flight across the barrier)
            if (slab + 1 < NSLAB) { n0 = ldnext(); n1 = ldnext(); }

            __syncthreads();

            // ---- horizontal 5-tap (dilated by D along x): uniform, branch-free ----
            #pragma unroll
            for (int r = 0; r < 2; r++) {
                const float* smrow = sm[buf][r];
                const float4 vc  = (r == 0) ? v0 : v1;
                const float4 raw = (r == 0) ? w0 : w1;
                float4 low;

                if constexpr (D >= 4) {
                    constexpr int G = D / 4;               // tap offset in f4 groups
                    const float4 a  = *reinterpret_cast<const float4*>(&smrow[xb - 8 * G]);
                    const float4 bb = *reinterpret_cast<const float4*>(&smrow[xb - 4 * G]);
                    const float4 d  = *reinterpret_cast<const float4*>(&smrow[xb + 4 * G]);
                    const float4 e  = *reinterpret_cast<const float4*>(&smrow[xb + 8 * G]);
                    low = vcomb(a, bb, vc, d, e);
                } else {
                    float fl[12];
                    *reinterpret_cast<float4*>(&fl[0]) = *reinterpret_cast<const float4*>(&smrow[xb - 4]);
                    fl[4] = vc.x; fl[5] = vc.y; fl[6] = vc.z; fl[7] = vc.w;
                    *reinterpret_cast<float4*>(&fl[8]) = *reinterpret_cast<const float4*>(&smrow[xb + 4]);
                    float lo[4];
                    #pragma unroll
                    for (int j = 0; j < 4; j++) {
                        lo[j] = W0 * (fl[4 + j - 2 * D] + fl[4 + j + 2 * D])
                              + W1 * (fl[4 + j - D]     + fl[4 + j + D])
                              + W2 *  fl[4 + j];
                    }
                    low.x = lo[0]; low.y = lo[1]; low.z = lo[2]; low.w = lo[3];
                }

                float4 cf;
                cf.x = (raw.x - low.x) * inv;
                cf.y = (raw.y - low.y) * inv;
                cf.z = (raw.z - low.z) * inv;
                cf.w = (raw.w - low.w) * inv;

                __stcs(reinterpret_cast<float4*>(cp), cf);   // streaming store
                cp += step;
                if (DST != 0) {
                    *reinterpret_cast<float4*>(lp) = low;    // keep in L2
                    lp += step;
                }
            }
            // double-buffered smem: no trailing barrier
        }
    };

    const int HWsub = HW / D;   // sub-image height
    if (s0 >= 2 && s0 + S + 2 <= HWsub) {
        // interior strip: pure incremental pointer, no reflection possible
        const float* p = simg + (size_t)(resid + D * (s0 - 2)) * HW + x4;
        run([&]() -> float4 {
            const float4 v = ld4(p);
            p += step;
            return v;
        });
    } else {
        // boundary strip: reflected row indices
        int s = s0 - 2;
        run([&]() -> float4 {
            const int f = refl(resid + D * s);
            s++;
            return ld4(simg + (size_t)f * HW + x4);
        });
    }
}

extern "C" void kernel_launch(void* const* d_in, const int* in_sizes, int n_in,
                              void* d_out, int out_size)
{
    int img_idx = 0, nrm_idx = 1;
    if (n_in >= 2 && in_sizes[0] == 4) { img_idx = 1; nrm_idx = 0; }

    const float* image = (const float*)d_in[img_idx];
    const float* norms = (const float*)d_in[nrm_idx];
    float* out = (float*)d_out;

    int B = in_sizes[img_idx] / PLANE;
    if (B < 1) B = 1;
    if (B > BMAX) B = BMAX;
    const size_t plane_all = (size_t)B * PLANE;

    const dim3 block(256);
    // grid: x = strips of 32 sub-rows, y = D residues, z = batch (512 blocks/scale)
    const dim3 g1(HW / (1 * 32), 1, B);
    const dim3 g2(HW / (2 * 32), 2, B);
    const dim3 g4(HW / (4 * 32), 4, B);
    const dim3 g8(HW / (8 * 32), 8, B);

    // scale 0: image (streaming read: read-once) -> lowA
    starlet_stream<1, 0, 1, true ><<<g1, block>>>(image, norms, 0, out + 0 * plane_all);
    // scale 1: lowA -> lowB (lowA stays cached: default read)
    starlet_stream<2, 1, 2, false><<<g2, block>>>(image, norms, 1, out + 1 * plane_all);
    // scale 2: lowB -> lowA
    starlet_stream<4, 2, 1, false><<<g4, block>>>(image, norms, 2, out + 2 * plane_all);
    // scale 3: lowA -> (none); last use of lowA -> streaming read
    starlet_stream<8, 1, 0, true ><<<g8, block>>>(image, norms, 3, out + 3 * plane_all);
}